// round 15
// baseline (speedup 1.0000x reference)
#include <cuda_runtime.h>
#include <cuda_bf16.h>
#include <cstdint>

// ---------------------------------------------------------------------------
// Problem constants
// ---------------------------------------------------------------------------
#define BATCH   2
#define CCH     256
#define LDIM    240
#define LW      20
#define NWH     12                 // windows per side
#define NWIN    288                // BATCH * 12 * 12
#define FPX     400                // LW*LW
#define NHEAD   8
#define HD      32
#define DFF     2048
#define LL      57600              // LDIM*LDIM
#define EPSLN   1e-5f
#define SCALING 0.17677669529663687f   // 32^-0.5

// scratch pool (float counts)
#define SZ_SRC2W  29491200ull          // NWIN*CCH*FPX
#define SZ_QKV    88473600ull          // 3x
#define POOL_FLOATS (SZ_SRC2W + SZ_QKV)
#define OFF_QKV   SZ_SRC2W
#define OFF_HID   SZ_SRC2W             // reuses QKV region (2048*14400 = 29491200)

__device__ float g_pool[POOL_FLOATS];
__device__ float g_res1[BATCH * CCH * LL];

// ---------------------------------------------------------------------------
// K1a: LayerNorm over C + window partition   src[B,C,L,L] -> src2w[w][c][p]
// ---------------------------------------------------------------------------
__global__ __launch_bounds__(256) void k_ln_win(
    const float* __restrict__ src, const float* __restrict__ g,
    const float* __restrict__ bt, float* __restrict__ dst)
{
    int y = blockIdx.x, b = blockIdx.y;
    int x = threadIdx.x;
    if (x >= LDIM) return;
    const float* p = src + (size_t)b * CCH * LL + (size_t)y * LDIM + x;
    float s = 0.f, s2 = 0.f;
    for (int c = 0; c < CCH; c++) {
        float v = p[(size_t)c * LL];
        s += v; s2 += v * v;
    }
    float m  = s * (1.f / CCH);
    float vr = s2 * (1.f / CCH) - m * m;
    float r  = rsqrtf(vr + EPSLN);
    int wdx = b * 144 + (y / LW) * NWH + (x / LW);
    int pp  = (y % LW) * LW + (x % LW);
    float* q = dst + (size_t)wdx * CCH * FPX + pp;
    for (int c = 0; c < CCH; c++)
        q[(size_t)c * FPX] = (p[(size_t)c * LL] - m) * r * g[c] + bt[c];
}

// K1b: LayerNorm over C, NCHW in, NCHW out
__global__ __launch_bounds__(256) void k_ln_nchw(
    const float* __restrict__ src, const float* __restrict__ g,
    const float* __restrict__ bt, float* __restrict__ dst)
{
    int y = blockIdx.x, b = blockIdx.y;
    int x = threadIdx.x;
    if (x >= LDIM) return;
    size_t base = (size_t)b * CCH * LL + (size_t)y * LDIM + x;
    const float* p = src + base;
    float s = 0.f, s2 = 0.f;
    for (int c = 0; c < CCH; c++) {
        float v = p[(size_t)c * LL];
        s += v; s2 += v * v;
    }
    float m  = s * (1.f / CCH);
    float vr = s2 * (1.f / CCH) - m * m;
    float r  = rsqrtf(vr + EPSLN);
    float* q = dst + base;
    for (int c = 0; c < CCH; c++)
        q[(size_t)c * LL] = (p[(size_t)c * LL] - m) * r * g[c] + bt[c];
}

// ---------------------------------------------------------------------------
// K2: 3x3 conv (pad=1) inside each 20x20 window  -> qkv[w][768][400]
//     GEMM-ish: BM=128 oc, BN=80 px, K chunks of 16 channels (x9 taps)
// ---------------------------------------------------------------------------
#define CONV_WS   (144 * 129)          // [cc*9+k][128] padded
#define CONV_XS   (16 * 400)
#define CONV_SMEM_BYTES ((CONV_WS + CONV_XS) * 4)

__global__ __launch_bounds__(256, 2) void k_conv_qkv(
    const float* __restrict__ xin, const float* __restrict__ wq,
    const float* __restrict__ bq, float* __restrict__ out)
{
    extern __shared__ float sm[];
    float* w_s  = sm;              // 144 x 128 (stride 129)
    float* in_s = sm + CONV_WS;    // 16 x 400

    int w   = blockIdx.z;
    int oc0 = blockIdx.y * 128;
    int px0 = blockIdx.x * 80;
    int tid = threadIdx.x;
    int tco = tid >> 4, tpx = tid & 15;

    int row[5], col[5], pabs[5];
#pragma unroll
    for (int j = 0; j < 5; j++) {
        pabs[j] = px0 + tpx + 16 * j;
        row[j]  = pabs[j] / LW;
        col[j]  = pabs[j] % LW;
    }

    float acc[8][5];
#pragma unroll
    for (int i = 0; i < 8; i++) {
        float bb = bq[oc0 + tco + 16 * i];
#pragma unroll
        for (int j = 0; j < 5; j++) acc[i][j] = bb;
    }

    const float* xbase = xin + (size_t)w * CCH * FPX;

    for (int c0 = 0; c0 < CCH; c0 += 16) {
#pragma unroll
        for (int m = 0; m < 72; m++) {              // 144*128 / 256
            int f   = m * 256 + tid;
            int ocl = f / 144, rem = f % 144;
            w_s[rem * 129 + ocl] = wq[(size_t)(oc0 + ocl) * 2304 + c0 * 9 + rem];
        }
#pragma unroll
        for (int m = 0; m < 25; m++) {              // 16*400 / 256
            int f = m * 256 + tid;
            in_s[f] = xbase[(size_t)c0 * FPX + f];
        }
        __syncthreads();

#pragma unroll
        for (int k = 0; k < 9; k++) {
            int dy = k / 3 - 1, dx = k % 3 - 1;
            int off[5]; bool ok[5];
#pragma unroll
            for (int j = 0; j < 5; j++) {
                int r = row[j] + dy, c = col[j] + dx;
                ok[j]  = (r >= 0) && (r < LW) && (c >= 0) && (c < LW);
                off[j] = r * LW + c;
            }
#pragma unroll
            for (int cc = 0; cc < 16; cc++) {
                float a[8], xv[5];
#pragma unroll
                for (int i = 0; i < 8; i++)
                    a[i] = w_s[(cc * 9 + k) * 129 + tco + 16 * i];
#pragma unroll
                for (int j = 0; j < 5; j++)
                    xv[j] = ok[j] ? in_s[cc * 400 + off[j]] : 0.f;
#pragma unroll
                for (int i = 0; i < 8; i++)
#pragma unroll
                    for (int j = 0; j < 5; j++)
                        acc[i][j] = fmaf(a[i], xv[j], acc[i][j]);
            }
        }
        __syncthreads();
    }

#pragma unroll
    for (int i = 0; i < 8; i++) {
        int oc = oc0 + tco + 16 * i;
        float* o = out + ((size_t)w * 768 + oc) * FPX;
#pragma unroll
        for (int j = 0; j < 5; j++) o[pabs[j]] = acc[i][j];
    }
}

// ---------------------------------------------------------------------------
// K3: windowed attention, one block per (head, window). K/V/Q in smem.
// ---------------------------------------------------------------------------
#define AT_RS 417                      // padded row stride (coprime with 32)
#define ATTN_SMEM_FLOATS (3 * 32 * AT_RS + 1521 + 8 * 416 + 400)
#define ATTN_SMEM_BYTES  (ATTN_SMEM_FLOATS * 4)

__global__ __launch_bounds__(256, 1) void k_attn(
    const float* __restrict__ qkv, const float* __restrict__ rpb,
    const unsigned char* __restrict__ pmask, float* __restrict__ outp)
{
    extern __shared__ float sm[];
    float* q_s    = sm;
    float* k_s    = q_s + 32 * AT_RS;
    float* v_s    = k_s + 32 * AT_RS;
    float* rpb_s  = v_s + 32 * AT_RS;       // 1521
    float* p_s    = rpb_s + 1521;           // 8 * 416
    float* mask_s = p_s + 8 * 416;          // 400
    __shared__ int s_cnt;

    int h = blockIdx.x, w = blockIdx.y;
    int tid = threadIdx.x;
    const size_t base = ((size_t)w * 768 + h * HD) * FPX;

    for (int f = tid; f < HD * FPX; f += 256) {
        int d = f / FPX, j = f % FPX;
        q_s[d * AT_RS + j] = qkv[base + f] * SCALING;
        k_s[d * AT_RS + j] = qkv[base + (size_t)CCH * FPX + f];
        v_s[d * AT_RS + j] = qkv[base + (size_t)2 * CCH * FPX + f];
    }
    for (int f = tid; f < 32 * (AT_RS - FPX); f += 256) {
        int d = f / (AT_RS - FPX), j = FPX + f % (AT_RS - FPX);
        q_s[d * AT_RS + j] = 0.f; k_s[d * AT_RS + j] = 0.f; v_s[d * AT_RS + j] = 0.f;
    }
    for (int t = tid; t < 1521; t += 256) rpb_s[t] = rpb[t * NHEAD + h];
    if (tid == 0) s_cnt = 0;
    __syncthreads();

    int b = w / 144, wy = (w % 144) / NWH, wx = w % NWH;
    int cnt = 0;
    for (int p = tid; p < FPX; p += 256) {
        int y = wy * LW + p / LW, x = wx * LW + p % LW;
        int m = pmask[(size_t)b * LL + (size_t)y * LDIM + x] ? 1 : 0;
        mask_s[p] = (float)m;
        cnt += m;
    }
    atomicAdd(&s_cnt, cnt);
    __syncthreads();
    bool fully = (s_cnt == FPX);
    for (int p = tid; p < FPX; p += 256)
        mask_s[p] = (!fully && mask_s[p] > 0.5f) ? -1e30f : 0.f;
    __syncthreads();

    int wi = tid >> 5, l = tid & 31;

    for (int t = 0; t < 50; t++) {
        int i  = wi + 8 * t;
        int ri = i / LW, ci = i % LW;
        float s[13];
#pragma unroll
        for (int m = 0; m < 13; m++) s[m] = 0.f;
#pragma unroll 4
        for (int d = 0; d < 32; d++) {
            float qd = q_s[d * AT_RS + i];
#pragma unroll
            for (int m = 0; m < 13; m++)
                s[m] = fmaf(qd, k_s[d * AT_RS + l + 32 * m], s[m]);
        }
        float mx = -1e30f;
#pragma unroll
        for (int m = 0; m < 13; m++) {
            int j = l + 32 * m;
            if (j < FPX) {
                int rj = j / LW, cj = j % LW;
                int dr = rj - ri; if (dr < 0) dr += 39;
                int dc = cj - ci; if (dc < 0) dc += 39;
                s[m] += rpb_s[dr * 39 + dc] + mask_s[j];
            } else s[m] = -1e30f;
            mx = fmaxf(mx, s[m]);
        }
#pragma unroll
        for (int o = 16; o > 0; o >>= 1)
            mx = fmaxf(mx, __shfl_xor_sync(0xffffffffu, mx, o));
        float sum = 0.f;
#pragma unroll
        for (int m = 0; m < 13; m++) { s[m] = __expf(s[m] - mx); sum += s[m]; }
#pragma unroll
        for (int o = 16; o > 0; o >>= 1)
            sum += __shfl_xor_sync(0xffffffffu, sum, o);
        float inv = 1.f / sum;
#pragma unroll
        for (int m = 0; m < 13; m++)
            p_s[wi * 416 + l + 32 * m] = s[m] * inv;
        __syncwarp();

        // AV: lane == d
        float acc = 0.f;
        const float* vrow = v_s + l * AT_RS;
        const float* prow = p_s + wi * 416;
#pragma unroll 8
        for (int j = 0; j < FPX; j++)
            acc = fmaf(prow[j], vrow[j], acc);
        outp[((size_t)w * CCH + h * HD + l) * FPX + i] = acc;
        __syncwarp();
    }
}

// ---------------------------------------------------------------------------
// K4: 1x1 out-proj + window merge + residual -> res1 (NCHW)
// ---------------------------------------------------------------------------
__global__ __launch_bounds__(256) void k_outproj(
    const float* __restrict__ ain, const float* __restrict__ wgt,
    const float* __restrict__ bias, const float* __restrict__ src,
    float* __restrict__ res)
{
    __shared__ float Ws[32 * 65];
    __shared__ float Xs[32 * 80];
    int w   = blockIdx.z;
    int co0 = blockIdx.y * 64;
    int px0 = blockIdx.x * 80;
    int tid = threadIdx.x, tco = tid >> 4, tpx = tid & 15;

    float acc[4][5];
#pragma unroll
    for (int i = 0; i < 4; i++)
#pragma unroll
        for (int j = 0; j < 5; j++) acc[i][j] = 0.f;

    for (int c0 = 0; c0 < CCH; c0 += 32) {
#pragma unroll
        for (int m = 0; m < 8; m++) {
            int f = m * 256 + tid;
            int cl = f >> 5, kk = f & 31;
            Ws[kk * 65 + cl] = wgt[(size_t)(co0 + cl) * CCH + c0 + kk];
        }
#pragma unroll
        for (int m = 0; m < 10; m++) {
            int f = m * 256 + tid;
            int kk = f / 80, pl = f % 80;
            Xs[kk * 80 + pl] = ain[((size_t)w * CCH + c0 + kk) * FPX + px0 + pl];
        }
        __syncthreads();
#pragma unroll
        for (int kk = 0; kk < 32; kk++) {
            float a[4], xv[5];
#pragma unroll
            for (int i = 0; i < 4; i++) a[i] = Ws[kk * 65 + tco + 16 * i];
#pragma unroll
            for (int j = 0; j < 5; j++) xv[j] = Xs[kk * 80 + tpx + 16 * j];
#pragma unroll
            for (int i = 0; i < 4; i++)
#pragma unroll
                for (int j = 0; j < 5; j++)
                    acc[i][j] = fmaf(a[i], xv[j], acc[i][j]);
        }
        __syncthreads();
    }

    int b = w / 144, wy = (w % 144) / NWH, wx = w % NWH;
#pragma unroll
    for (int i = 0; i < 4; i++) {
        int co  = co0 + tco + 16 * i;
        float bb = bias[co];
#pragma unroll
        for (int j = 0; j < 5; j++) {
            int p = px0 + tpx + 16 * j;
            int y = wy * LW + p / LW;
            int x = wx * LW + p % LW;
            size_t idx = ((size_t)(b * CCH + co) * LDIM + y) * LDIM + x;
            res[idx] = src[idx] + acc[i][j] + bb;
        }
    }
}

// ---------------------------------------------------------------------------
// K6: FFN1  h = relu(W1 x + b1)  over a pixel chunk of 14400 (per batch)
// ---------------------------------------------------------------------------
__global__ __launch_bounds__(256, 2) void k_ffn1(
    const float* __restrict__ x, const float* __restrict__ w1,
    const float* __restrict__ b1, float* __restrict__ hid,
    int b, int p0)
{
    __shared__ float Ws[16 * 129];
    __shared__ float Xs[16 * 80];
    int px0 = blockIdx.x * 80;
    int co0 = blockIdx.y * 128;
    int tid = threadIdx.x, tco = tid >> 4, tpx = tid & 15;

    float acc[8][5];
#pragma unroll
    for (int i = 0; i < 8; i++)
#pragma unroll
        for (int j = 0; j < 5; j++) acc[i][j] = 0.f;

    for (int c0 = 0; c0 < CCH; c0 += 16) {
#pragma unroll
        for (int m = 0; m < 8; m++) {
            int f = m * 256 + tid;
            int cl = f >> 4, kk = f & 15;
            Ws[kk * 129 + cl] = w1[(size_t)(co0 + cl) * CCH + c0 + kk];
        }
#pragma unroll
        for (int m = 0; m < 5; m++) {
            int f = m * 256 + tid;
            int kk = f / 80, pl = f % 80;
            Xs[kk * 80 + pl] = x[(size_t)(b * CCH + c0 + kk) * LL + p0 + px0 + pl];
        }
        __syncthreads();
#pragma unroll
        for (int kk = 0; kk < 16; kk++) {
            float a[8], xv[5];
#pragma unroll
            for (int i = 0; i < 8; i++) a[i] = Ws[kk * 129 + tco + 16 * i];
#pragma unroll
            for (int j = 0; j < 5; j++) xv[j] = Xs[kk * 80 + tpx + 16 * j];
#pragma unroll
            for (int i = 0; i < 8; i++)
#pragma unroll
                for (int j = 0; j < 5; j++)
                    acc[i][j] = fmaf(a[i], xv[j], acc[i][j]);
        }
        __syncthreads();
    }

#pragma unroll
    for (int i = 0; i < 8; i++) {
        int co = co0 + tco + 16 * i;
        float bb = b1[co];
#pragma unroll
        for (int j = 0; j < 5; j++) {
            int pl = px0 + tpx + 16 * j;
            hid[(size_t)co * 14400 + pl] = fmaxf(acc[i][j] + bb, 0.f);
        }
    }
}

// ---------------------------------------------------------------------------
// K7: FFN2 + residual + final padding mask -> d_out
// ---------------------------------------------------------------------------
__global__ __launch_bounds__(256, 2) void k_ffn2(
    const float* __restrict__ hid, const float* __restrict__ w2,
    const float* __restrict__ b2, const float* __restrict__ res1,
    const unsigned char* __restrict__ pmask, float* __restrict__ out,
    int b, int p0)
{
    __shared__ float Ws[16 * 129];
    __shared__ float Xs[16 * 80];
    int px0 = blockIdx.x * 80;
    int co0 = blockIdx.y * 128;
    int tid = threadIdx.x, tco = tid >> 4, tpx = tid & 15;

    float acc[8][5];
#pragma unroll
    for (int i = 0; i < 8; i++)
#pragma unroll
        for (int j = 0; j < 5; j++) acc[i][j] = 0.f;

    for (int c0 = 0; c0 < DFF; c0 += 16) {
#pragma unroll
        for (int m = 0; m < 8; m++) {
            int f = m * 256 + tid;
            int cl = f >> 4, kk = f & 15;
            Ws[kk * 129 + cl] = w2[(size_t)(co0 + cl) * DFF + c0 + kk];
        }
#pragma unroll
        for (int m = 0; m < 5; m++) {
            int f = m * 256 + tid;
            int kk = f / 80, pl = f % 80;
            Xs[kk * 80 + pl] = hid[(size_t)(c0 + kk) * 14400 + px0 + pl];
        }
        __syncthreads();
#pragma unroll
        for (int kk = 0; kk < 16; kk++) {
            float a[8], xv[5];
#pragma unroll
            for (int i = 0; i < 8; i++) a[i] = Ws[kk * 129 + tco + 16 * i];
#pragma unroll
            for (int j = 0; j < 5; j++) xv[j] = Xs[kk * 80 + tpx + 16 * j];
#pragma unroll
            for (int i = 0; i < 8; i++)
#pragma unroll
                for (int j = 0; j < 5; j++)
                    acc[i][j] = fmaf(a[i], xv[j], acc[i][j]);
        }
        __syncthreads();
    }

#pragma unroll
    for (int i = 0; i < 8; i++) {
        int co = co0 + tco + 16 * i;
        float bb = b2[co];
#pragma unroll
        for (int j = 0; j < 5; j++) {
            int pl  = px0 + tpx + 16 * j;
            int pix = p0 + pl;
            unsigned char mflag = pmask[(size_t)b * LL + pix];
            size_t idx = (size_t)(b * CCH + co) * LL + pix;
            out[idx] = mflag ? 0.f : (res1[idx] + acc[i][j] + bb);
        }
    }
}

// ---------------------------------------------------------------------------
// Host launcher
// ---------------------------------------------------------------------------
extern "C" void kernel_launch(void* const* d_in, const int* in_sizes, int n_in,
                              void* d_out, int out_size)
{
    const float*         src   = (const float*)d_in[0];
    const unsigned char* pmask = (const unsigned char*)d_in[1];
    const float* n1w  = (const float*)d_in[2];
    const float* n1b  = (const float*)d_in[3];
    const float* qkvw = (const float*)d_in[4];
    const float* qkvb = (const float*)d_in[5];
    const float* outw = (const float*)d_in[6];
    const float* outb = (const float*)d_in[7];
    const float* rpb  = (const float*)d_in[8];
    const float* n2w  = (const float*)d_in[9];
    const float* n2b  = (const float*)d_in[10];
    const float* l1w  = (const float*)d_in[11];
    const float* l1b  = (const float*)d_in[12];
    const float* l2w  = (const float*)d_in[13];
    const float* l2b  = (const float*)d_in[14];
    float* outp = (float*)d_out;

    float *pool, *res1;
    cudaGetSymbolAddress((void**)&pool, g_pool);
    cudaGetSymbolAddress((void**)&res1, g_res1);

    float* src2w = pool;                 // [288][256][400]
    float* qkv   = pool + OFF_QKV;       // [288][768][400]
    float* attno = pool;                 // reuse (src2w dead after conv)
    float* ln2   = pool;                 // reuse (attno dead after outproj)
    float* hid   = pool + OFF_HID;       // reuse (qkv dead after attention)

    cudaFuncSetAttribute(k_conv_qkv, cudaFuncAttributeMaxDynamicSharedMemorySize,
                         CONV_SMEM_BYTES);
    cudaFuncSetAttribute(k_attn, cudaFuncAttributeMaxDynamicSharedMemorySize,
                         ATTN_SMEM_BYTES);

    // 1. LN1 + window partition
    k_ln_win<<<dim3(LDIM, BATCH), 256>>>(src, n1w, n1b, src2w);

    // 2. windowed 3x3 conv QKV
    k_conv_qkv<<<dim3(5, 6, NWIN), 256, CONV_SMEM_BYTES>>>(src2w, qkvw, qkvb, qkv);

    // 3. attention per (head, window)
    k_attn<<<dim3(NHEAD, NWIN), 256, ATTN_SMEM_BYTES>>>(qkv, rpb, pmask, attno);

    // 4. out-proj + merge + residual
    k_outproj<<<dim3(5, 4, NWIN), 256>>>(attno, outw, outb, src, res1);

    // 5. LN2
    k_ln_nchw<<<dim3(LDIM, BATCH), 256>>>(res1, n2w, n2b, ln2);

    // 6/7. FFN in pixel chunks of 14400 (hidden reuses pool)
    for (int b = 0; b < BATCH; b++) {
        for (int ch = 0; ch < 4; ch++) {
            int p0 = ch * 14400;
            k_ffn1<<<dim3(180, 16), 256>>>(ln2, l1w, l1b, hid, b, p0);
            k_ffn2<<<dim3(180, 2),  256>>>(hid, l2w, l2b, res1, pmask, outp, b, p0);
        }
    }
}

// round 16
// speedup vs baseline: 2.6776x; 2.6776x over previous
#include <cuda_runtime.h>
#include <cuda_bf16.h>
#include <cstdint>

// ---------------------------------------------------------------------------
// Problem constants
// ---------------------------------------------------------------------------
#define BATCH   2
#define CCH     256
#define LDIM    240
#define LW      20
#define NWH     12                 // windows per side
#define NWIN    288                // BATCH * 12 * 12
#define FPX     400                // LW*LW
#define NHEAD   8
#define HD      32
#define DFF     2048
#define LL      57600              // LDIM*LDIM
#define EPSLN   1e-5f
#define SCALING 0.17677669529663687f   // 32^-0.5

// scratch pool (float counts)
#define SZ_SRC2W  29491200ull          // NWIN*CCH*FPX
#define SZ_HID    117964800ull         // DFF * LL (one batch)
#define POOL_FLOATS (SZ_SRC2W + SZ_HID)
#define OFF_QKV   SZ_SRC2W             // qkv needs 88473600 <= SZ_HID
#define OFF_HID   SZ_SRC2W

__device__ float g_pool[POOL_FLOATS];
__device__ float g_res1[BATCH * CCH * LL];

// ---------------------------------------------------------------------------
// tf32 mma helpers
// ---------------------------------------------------------------------------
__device__ __forceinline__ uint32_t f2t(float f) {
    uint32_t u;
    asm("cvt.rna.tf32.f32 %0, %1;" : "=r"(u) : "f"(f));
    return u;
}

__device__ __forceinline__ void mma_tf32(float* c, const uint32_t* a,
                                         uint32_t b0, uint32_t b1) {
    asm volatile(
        "mma.sync.aligned.m16n8k8.row.col.f32.tf32.tf32.f32 "
        "{%0,%1,%2,%3}, {%4,%5,%6,%7}, {%8,%9}, {%0,%1,%2,%3};\n"
        : "+f"(c[0]), "+f"(c[1]), "+f"(c[2]), "+f"(c[3])
        : "r"(a[0]), "r"(a[1]), "r"(a[2]), "r"(a[3]), "r"(b0), "r"(b1));
}

// ---------------------------------------------------------------------------
// K1a: LayerNorm over C + window partition   src[B,C,L,L] -> src2w[w][c][p]
// ---------------------------------------------------------------------------
__global__ __launch_bounds__(256) void k_ln_win(
    const float* __restrict__ src, const float* __restrict__ g,
    const float* __restrict__ bt, float* __restrict__ dst)
{
    int y = blockIdx.x, b = blockIdx.y;
    int x = threadIdx.x;
    if (x >= LDIM) return;
    const float* p = src + (size_t)b * CCH * LL + (size_t)y * LDIM + x;
    float s = 0.f, s2 = 0.f;
    for (int c = 0; c < CCH; c++) {
        float v = p[(size_t)c * LL];
        s += v; s2 += v * v;
    }
    float m  = s * (1.f / CCH);
    float vr = s2 * (1.f / CCH) - m * m;
    float r  = rsqrtf(vr + EPSLN);
    int wdx = b * 144 + (y / LW) * NWH + (x / LW);
    int pp  = (y % LW) * LW + (x % LW);
    float* q = dst + (size_t)wdx * CCH * FPX + pp;
    for (int c = 0; c < CCH; c++)
        q[(size_t)c * FPX] = (p[(size_t)c * LL] - m) * r * g[c] + bt[c];
}

// K1b: LayerNorm over C, NCHW in, NCHW out
__global__ __launch_bounds__(256) void k_ln_nchw(
    const float* __restrict__ src, const float* __restrict__ g,
    const float* __restrict__ bt, float* __restrict__ dst)
{
    int y = blockIdx.x, b = blockIdx.y;
    int x = threadIdx.x;
    if (x >= LDIM) return;
    size_t base = (size_t)b * CCH * LL + (size_t)y * LDIM + x;
    const float* p = src + base;
    float s = 0.f, s2 = 0.f;
    for (int c = 0; c < CCH; c++) {
        float v = p[(size_t)c * LL];
        s += v; s2 += v * v;
    }
    float m  = s * (1.f / CCH);
    float vr = s2 * (1.f / CCH) - m * m;
    float r  = rsqrtf(vr + EPSLN);
    float* q = dst + base;
    for (int c = 0; c < CCH; c++)
        q[(size_t)c * LL] = (p[(size_t)c * LL] - m) * r * g[c] + bt[c];
}

// ---------------------------------------------------------------------------
// K2: windowed 3x3 conv QKV as implicit GEMM with tf32 mma
//     C[768,400] = W[768, 2304] x im2col(X)[2304, 400] per window
//     Block: 128 oc x 80 px, K chunks of 72 (8 channels x 9 taps)
// ---------------------------------------------------------------------------
#define CV_AS_STRIDE 76
#define CV_BS_STRIDE 88
#define CV_AS (128 * CV_AS_STRIDE)
#define CV_BS (72 * CV_BS_STRIDE)
#define CV_SMEM_BYTES ((CV_AS + CV_BS) * 4)

__global__ __launch_bounds__(256, 2) void k_conv_mma(
    const float* __restrict__ xin, const float* __restrict__ wq,
    const float* __restrict__ bq, float* __restrict__ out)
{
    extern __shared__ uint32_t sm[];
    uint32_t* A_s = sm;              // [128][76] (72 used)
    uint32_t* B_s = sm + CV_AS;      // [72][88]  (80 used)

    int w   = blockIdx.z;
    int oc0 = blockIdx.y * 128;
    int px0 = blockIdx.x * 80;
    int tid  = threadIdx.x;
    int lane = tid & 31, wid = tid >> 5;
    int warp_m = wid >> 1;           // 0..3 -> 32 oc each
    int warp_n = wid & 1;            // 0..1 -> 40 px each

    float acc[2][5][4];
#pragma unroll
    for (int mt = 0; mt < 2; mt++)
#pragma unroll
        for (int nt = 0; nt < 5; nt++)
#pragma unroll
            for (int r = 0; r < 4; r++) acc[mt][nt][r] = 0.f;

    // B-build precompute: thread -> (tap-row group g, pixel pxl)
    int g    = tid / 80;             // 0..2 valid (tid < 240)
    int pxl  = tid - g * 80;
    int pabs = px0 + pxl;
    int row0 = pabs / LW, col0 = pabs % LW;
    int rB   = row0 + (g - 1);
    bool rok = (rB >= 0) && (rB < LW) && (tid < 240);
    bool okc[3];
    int  offt[3];
#pragma unroll
    for (int tt = 0; tt < 3; tt++) {
        int cc   = col0 + tt - 1;
        okc[tt]  = rok && (cc >= 0) && (cc < LW);
        offt[tt] = rB * LW + cc;
    }

    const float* xb = xin + (size_t)w * CCH * FPX;
    int arow = tid >> 1, ahalf = tid & 1;

    for (int c0 = 0; c0 < CCH; c0 += 8) {
        // ---- stage A (weights, tf32): row arow, half ahalf (9 f4 each) ----
        const float* wr = wq + (size_t)(oc0 + arow) * 2304 + c0 * 9 + ahalf * 36;
        uint32_t*    ar = A_s + arow * CV_AS_STRIDE + ahalf * 36;
#pragma unroll
        for (int i = 0; i < 9; i++) {
            float4 v = *(const float4*)(wr + i * 4);
            uint4 u; u.x = f2t(v.x); u.y = f2t(v.y); u.z = f2t(v.z); u.w = f2t(v.w);
            *(uint4*)(ar + i * 4) = u;
        }
        // ---- build B (im2col, tf32) straight from gmem ----
        if (tid < 240) {
#pragma unroll 2
            for (int c = 0; c < 8; c++) {
                const float* xr = xb + (size_t)(c0 + c) * FPX;
#pragma unroll
                for (int tt = 0; tt < 3; tt++) {
                    float v = okc[tt] ? xr[offt[tt]] : 0.f;
                    B_s[(c * 9 + g * 3 + tt) * CV_BS_STRIDE + pxl] = f2t(v);
                }
            }
        }
        __syncthreads();

        // ---- compute: 9 k8-steps ----
#pragma unroll
        for (int ks = 0; ks < 9; ks++) {
            uint32_t a[2][4];
#pragma unroll
            for (int mt = 0; mt < 2; mt++) {
                int base = (warp_m * 32 + mt * 16 + (lane >> 2)) * CV_AS_STRIDE
                         + ks * 8 + (lane & 3);
                a[mt][0] = A_s[base];
                a[mt][1] = A_s[base + 8 * CV_AS_STRIDE];
                a[mt][2] = A_s[base + 4];
                a[mt][3] = A_s[base + 8 * CV_AS_STRIDE + 4];
            }
            int rb = ks * 8 + (lane & 3);
#pragma unroll
            for (int nt = 0; nt < 5; nt++) {
                int n = warp_n * 40 + nt * 8 + (lane >> 2);
                uint32_t b0 = B_s[rb * CV_BS_STRIDE + n];
                uint32_t b1 = B_s[(rb + 4) * CV_BS_STRIDE + n];
#pragma unroll
                for (int mt = 0; mt < 2; mt++)
                    mma_tf32(acc[mt][nt], a[mt], b0, b1);
            }
        }
        __syncthreads();
    }

    // ---- epilogue: add bias, write float2 pairs ----
#pragma unroll
    for (int mt = 0; mt < 2; mt++) {
        int m = oc0 + warp_m * 32 + mt * 16 + (lane >> 2);
        float bv0 = bq[m], bv1 = bq[m + 8];
#pragma unroll
        for (int nt = 0; nt < 5; nt++) {
            int px = px0 + warp_n * 40 + nt * 8 + 2 * (lane & 3);
            float2 o0 = make_float2(acc[mt][nt][0] + bv0, acc[mt][nt][1] + bv0);
            float2 o1 = make_float2(acc[mt][nt][2] + bv1, acc[mt][nt][3] + bv1);
            *(float2*)&out[((size_t)w * 768 + m) * FPX + px]     = o0;
            *(float2*)&out[((size_t)w * 768 + m + 8) * FPX + px] = o1;
        }
    }
}

// ---------------------------------------------------------------------------
// K3: windowed attention, one block per (head, window). K/V/Q in smem.
// ---------------------------------------------------------------------------
#define AT_RS 417                      // padded row stride (coprime with 32)
#define ATTN_SMEM_FLOATS (3 * 32 * AT_RS + 1521 + 8 * 416 + 400)
#define ATTN_SMEM_BYTES  (ATTN_SMEM_FLOATS * 4)

__global__ __launch_bounds__(256, 1) void k_attn(
    const float* __restrict__ qkv, const float* __restrict__ rpb,
    const unsigned char* __restrict__ pmask, float* __restrict__ outp)
{
    extern __shared__ float smf[];
    float* q_s    = smf;
    float* k_s    = q_s + 32 * AT_RS;
    float* v_s    = k_s + 32 * AT_RS;
    float* rpb_s  = v_s + 32 * AT_RS;       // 1521
    float* p_s    = rpb_s + 1521;           // 8 * 416
    float* mask_s = p_s + 8 * 416;          // 400
    __shared__ int s_cnt;

    int h = blockIdx.x, w = blockIdx.y;
    int tid = threadIdx.x;
    const size_t base = ((size_t)w * 768 + h * HD) * FPX;

    for (int f = tid; f < HD * FPX; f += 256) {
        int d = f / FPX, j = f % FPX;
        q_s[d * AT_RS + j] = qkv[base + f] * SCALING;
        k_s[d * AT_RS + j] = qkv[base + (size_t)CCH * FPX + f];
        v_s[d * AT_RS + j] = qkv[base + (size_t)2 * CCH * FPX + f];
    }
    for (int f = tid; f < 32 * (AT_RS - FPX); f += 256) {
        int d = f / (AT_RS - FPX), j = FPX + f % (AT_RS - FPX);
        q_s[d * AT_RS + j] = 0.f; k_s[d * AT_RS + j] = 0.f; v_s[d * AT_RS + j] = 0.f;
    }
    for (int t = tid; t < 1521; t += 256) rpb_s[t] = rpb[t * NHEAD + h];
    if (tid == 0) s_cnt = 0;
    __syncthreads();

    int b = w / 144, wy = (w % 144) / NWH, wx = w % NWH;
    int cnt = 0;
    for (int p = tid; p < FPX; p += 256) {
        int y = wy * LW + p / LW, x = wx * LW + p % LW;
        int m = pmask[(size_t)b * LL + (size_t)y * LDIM + x] ? 1 : 0;
        mask_s[p] = (float)m;
        cnt += m;
    }
    atomicAdd(&s_cnt, cnt);
    __syncthreads();
    bool fully = (s_cnt == FPX);
    for (int p = tid; p < FPX; p += 256)
        mask_s[p] = (!fully && mask_s[p] > 0.5f) ? -1e30f : 0.f;
    __syncthreads();

    int wi = tid >> 5, l = tid & 31;

    for (int t = 0; t < 50; t++) {
        int i  = wi + 8 * t;
        int ri = i / LW, ci = i % LW;
        float s[13];
#pragma unroll
        for (int m = 0; m < 13; m++) s[m] = 0.f;
#pragma unroll 4
        for (int d = 0; d < 32; d++) {
            float qd = q_s[d * AT_RS + i];
#pragma unroll
            for (int m = 0; m < 13; m++)
                s[m] = fmaf(qd, k_s[d * AT_RS + l + 32 * m], s[m]);
        }
        float mx = -1e30f;
#pragma unroll
        for (int m = 0; m < 13; m++) {
            int j = l + 32 * m;
            if (j < FPX) {
                int rj = j / LW, cj = j % LW;
                int dr = rj - ri; if (dr < 0) dr += 39;
                int dc = cj - ci; if (dc < 0) dc += 39;
                s[m] += rpb_s[dr * 39 + dc] + mask_s[j];
            } else s[m] = -1e30f;
            mx = fmaxf(mx, s[m]);
        }
#pragma unroll
        for (int o = 16; o > 0; o >>= 1)
            mx = fmaxf(mx, __shfl_xor_sync(0xffffffffu, mx, o));
        float sum = 0.f;
#pragma unroll
        for (int m = 0; m < 13; m++) { s[m] = __expf(s[m] - mx); sum += s[m]; }
#pragma unroll
        for (int o = 16; o > 0; o >>= 1)
            sum += __shfl_xor_sync(0xffffffffu, sum, o);
        float inv = 1.f / sum;
#pragma unroll
        for (int m = 0; m < 13; m++)
            p_s[wi * 416 + l + 32 * m] = s[m] * inv;
        __syncwarp();

        // AV: lane == d
        float acc = 0.f;
        const float* vrow = v_s + l * AT_RS;
        const float* prow = p_s + wi * 416;
#pragma unroll 8
        for (int j = 0; j < FPX; j++)
            acc = fmaf(prow[j], vrow[j], acc);
        outp[((size_t)w * CCH + h * HD + l) * FPX + i] = acc;
        __syncwarp();
    }
}

// ---------------------------------------------------------------------------
// K4: 1x1 out-proj + window merge + residual -> res1 (NCHW)
// ---------------------------------------------------------------------------
__global__ __launch_bounds__(256) void k_outproj(
    const float* __restrict__ ain, const float* __restrict__ wgt,
    const float* __restrict__ bias, const float* __restrict__ src,
    float* __restrict__ res)
{
    __shared__ float Ws[32 * 65];
    __shared__ float Xs[32 * 80];
    int w   = blockIdx.z;
    int co0 = blockIdx.y * 64;
    int px0 = blockIdx.x * 80;
    int tid = threadIdx.x, tco = tid >> 4, tpx = tid & 15;

    float acc[4][5];
#pragma unroll
    for (int i = 0; i < 4; i++)
#pragma unroll
        for (int j = 0; j < 5; j++) acc[i][j] = 0.f;

    for (int c0 = 0; c0 < CCH; c0 += 32) {
#pragma unroll
        for (int m = 0; m < 8; m++) {
            int f = m * 256 + tid;
            int cl = f >> 5, kk = f & 31;
            Ws[kk * 65 + cl] = wgt[(size_t)(co0 + cl) * CCH + c0 + kk];
        }
#pragma unroll
        for (int m = 0; m < 10; m++) {
            int f = m * 256 + tid;
            int kk = f / 80, pl = f % 80;
            Xs[kk * 80 + pl] = ain[((size_t)w * CCH + c0 + kk) * FPX + px0 + pl];
        }
        __syncthreads();
#pragma unroll
        for (int kk = 0; kk < 32; kk++) {
            float a[4], xv[5];
#pragma unroll
            for (int i = 0; i < 4; i++) a[i] = Ws[kk * 65 + tco + 16 * i];
#pragma unroll
            for (int j = 0; j < 5; j++) xv[j] = Xs[kk * 80 + tpx + 16 * j];
#pragma unroll
            for (int i = 0; i < 4; i++)
#pragma unroll
                for (int j = 0; j < 5; j++)
                    acc[i][j] = fmaf(a[i], xv[j], acc[i][j]);
        }
        __syncthreads();
    }

    int b = w / 144, wy = (w % 144) / NWH, wx = w % NWH;
#pragma unroll
    for (int i = 0; i < 4; i++) {
        int co  = co0 + tco + 16 * i;
        float bb = bias[co];
#pragma unroll
        for (int j = 0; j < 5; j++) {
            int p = px0 + tpx + 16 * j;
            int y = wy * LW + p / LW;
            int x = wx * LW + p % LW;
            size_t idx = ((size_t)(b * CCH + co) * LDIM + y) * LDIM + x;
            res[idx] = src[idx] + acc[i][j] + bb;
        }
    }
}

// ---------------------------------------------------------------------------
// K6: FFN1 via tf32 mma:  hid = relu(W1 x + b1),  [2048,256] x [256,57600]
// Block 128x128, K chunks of 32. Grid (450, 16) per batch.
// ---------------------------------------------------------------------------
#define F_AS_STRIDE 36
#define F_BS_STRIDE 136

__global__ __launch_bounds__(256, 2) void k_ffn1_mma(
    const float* __restrict__ x, const float* __restrict__ w1,
    const float* __restrict__ b1, float* __restrict__ hid, int b)
{
    __shared__ uint32_t A_s[128 * F_AS_STRIDE];
    __shared__ uint32_t B_s[32 * F_BS_STRIDE];

    int px0 = blockIdx.x * 128;
    int co0 = blockIdx.y * 128;
    int tid  = threadIdx.x;
    int lane = tid & 31, wid = tid >> 5;
    int warp_m = wid >> 2;           // 0..1 -> 64 rows
    int warp_n = wid & 3;            // 0..3 -> 32 cols

    float acc[4][4][4];
#pragma unroll
    for (int mt = 0; mt < 4; mt++)
#pragma unroll
        for (int nt = 0; nt < 4; nt++)
#pragma unroll
            for (int r = 0; r < 4; r++) acc[mt][nt][r] = 0.f;

    for (int c0 = 0; c0 < CCH; c0 += 32) {
#pragma unroll
        for (int i = 0; i < 4; i++) {
            int f = i * 256 + tid;
            int row = f >> 3, j = f & 7;
            float4 v = *(const float4*)(w1 + (size_t)(co0 + row) * CCH + c0 + j * 4);
            uint4 u; u.x = f2t(v.x); u.y = f2t(v.y); u.z = f2t(v.z); u.w = f2t(v.w);
            *(uint4*)(A_s + row * F_AS_STRIDE + j * 4) = u;
        }
#pragma unroll
        for (int i = 0; i < 4; i++) {
            int f = i * 256 + tid;
            int row = f >> 5, j = f & 31;
            float4 v = *(const float4*)(x + (size_t)(b * CCH + c0 + row) * LL + px0 + j * 4);
            uint4 u; u.x = f2t(v.x); u.y = f2t(v.y); u.z = f2t(v.z); u.w = f2t(v.w);
            *(uint4*)(B_s + row * F_BS_STRIDE + j * 4) = u;
        }
        __syncthreads();

#pragma unroll
        for (int ks = 0; ks < 4; ks++) {
            uint32_t a[4][4];
#pragma unroll
            for (int mt = 0; mt < 4; mt++) {
                int base = (warp_m * 64 + mt * 16 + (lane >> 2)) * F_AS_STRIDE
                         + ks * 8 + (lane & 3);
                a[mt][0] = A_s[base];
                a[mt][1] = A_s[base + 8 * F_AS_STRIDE];
                a[mt][2] = A_s[base + 4];
                a[mt][3] = A_s[base + 8 * F_AS_STRIDE + 4];
            }
            int rb = ks * 8 + (lane & 3);
#pragma unroll
            for (int nt = 0; nt < 4; nt++) {
                int n = warp_n * 32 + nt * 8 + (lane >> 2);
                uint32_t b0 = B_s[rb * F_BS_STRIDE + n];
                uint32_t b1 = B_s[(rb + 4) * F_BS_STRIDE + n];
#pragma unroll
                for (int mt = 0; mt < 4; mt++)
                    mma_tf32(acc[mt][nt], a[mt], b0, b1);
            }
        }
        __syncthreads();
    }

#pragma unroll
    for (int mt = 0; mt < 4; mt++) {
        int m = co0 + warp_m * 64 + mt * 16 + (lane >> 2);
        float bv0 = b1[m], bv1 = b1[m + 8];
#pragma unroll
        for (int nt = 0; nt < 4; nt++) {
            int n = px0 + warp_n * 32 + nt * 8 + 2 * (lane & 3);
            float2 o0 = make_float2(fmaxf(acc[mt][nt][0] + bv0, 0.f),
                                    fmaxf(acc[mt][nt][1] + bv0, 0.f));
            float2 o1 = make_float2(fmaxf(acc[mt][nt][2] + bv1, 0.f),
                                    fmaxf(acc[mt][nt][3] + bv1, 0.f));
            *(float2*)&hid[(size_t)m * LL + n]       = o0;
            *(float2*)&hid[(size_t)(m + 8) * LL + n] = o1;
        }
    }
}

// ---------------------------------------------------------------------------
// K7: FFN2 via tf32 mma + residual + padding mask -> d_out
//     [256,2048] x [2048,57600]. Grid (450, 2) per batch.
// ---------------------------------------------------------------------------
__global__ __launch_bounds__(256, 2) void k_ffn2_mma(
    const float* __restrict__ hid, const float* __restrict__ w2,
    const float* __restrict__ b2, const float* __restrict__ res1,
    const unsigned char* __restrict__ pmask, float* __restrict__ out, int b)
{
    __shared__ uint32_t A_s[128 * F_AS_STRIDE];
    __shared__ uint32_t B_s[32 * F_BS_STRIDE];

    int px0 = blockIdx.x * 128;
    int co0 = blockIdx.y * 128;
    int tid  = threadIdx.x;
    int lane = tid & 31, wid = tid >> 5;
    int warp_m = wid >> 2;
    int warp_n = wid & 3;

    float acc[4][4][4];
#pragma unroll
    for (int mt = 0; mt < 4; mt++)
#pragma unroll
        for (int nt = 0; nt < 4; nt++)
#pragma unroll
            for (int r = 0; r < 4; r++) acc[mt][nt][r] = 0.f;

    for (int c0 = 0; c0 < DFF; c0 += 32) {
#pragma unroll
        for (int i = 0; i < 4; i++) {
            int f = i * 256 + tid;
            int row = f >> 3, j = f & 7;
            float4 v = *(const float4*)(w2 + (size_t)(co0 + row) * DFF + c0 + j * 4);
            uint4 u; u.x = f2t(v.x); u.y = f2t(v.y); u.z = f2t(v.z); u.w = f2t(v.w);
            *(uint4*)(A_s + row * F_AS_STRIDE + j * 4) = u;
        }
#pragma unroll
        for (int i = 0; i < 4; i++) {
            int f = i * 256 + tid;
            int row = f >> 5, j = f & 31;
            float4 v = *(const float4*)(hid + (size_t)(c0 + row) * LL + px0 + j * 4);
            uint4 u; u.x = f2t(v.x); u.y = f2t(v.y); u.z = f2t(v.z); u.w = f2t(v.w);
            *(uint4*)(B_s + row * F_BS_STRIDE + j * 4) = u;
        }
        __syncthreads();

#pragma unroll
        for (int ks = 0; ks < 4; ks++) {
            uint32_t a[4][4];
#pragma unroll
            for (int mt = 0; mt < 4; mt++) {
                int base = (warp_m * 64 + mt * 16 + (lane >> 2)) * F_AS_STRIDE
                         + ks * 8 + (lane & 3);
                a[mt][0] = A_s[base];
                a[mt][1] = A_s[base + 8 * F_AS_STRIDE];
                a[mt][2] = A_s[base + 4];
                a[mt][3] = A_s[base + 8 * F_AS_STRIDE + 4];
            }
            int rb = ks * 8 + (lane & 3);
#pragma unroll
            for (int nt = 0; nt < 4; nt++) {
                int n = warp_n * 32 + nt * 8 + (lane >> 2);
                uint32_t b0 = B_s[rb * F_BS_STRIDE + n];
                uint32_t b1 = B_s[(rb + 4) * F_BS_STRIDE + n];
#pragma unroll
                for (int mt = 0; mt < 4; mt++)
                    mma_tf32(acc[mt][nt], a[mt], b0, b1);
            }
        }
        __syncthreads();
    }

#pragma unroll
    for (int mt = 0; mt < 4; mt++) {
        int m = co0 + warp_m * 64 + mt * 16 + (lane >> 2);
        float bv0 = b2[m], bv1 = b2[m + 8];
#pragma unroll
        for (int nt = 0; nt < 4; nt++) {
            int n = px0 + warp_n * 32 + nt * 8 + 2 * (lane & 3);
            unsigned char mk0 = pmask[(size_t)b * LL + n];
            unsigned char mk1 = pmask[(size_t)b * LL + n + 1];
            size_t i0 = (size_t)(b * CCH + m) * LL + n;
            size_t i1 = (size_t)(b * CCH + m + 8) * LL + n;
            float2 r0 = *(const float2*)&res1[i0];
            float2 r1 = *(const float2*)&res1[i1];
            float2 o0, o1;
            o0.x = mk0 ? 0.f : (r0.x + acc[mt][nt][0] + bv0);
            o0.y = mk1 ? 0.f : (r0.y + acc[mt][nt][1] + bv0);
            o1.x = mk0 ? 0.f : (r1.x + acc[mt][nt][2] + bv1);
            o1.y = mk1 ? 0.f : (r1.y + acc[mt][nt][3] + bv1);
            *(float2*)&out[i0] = o0;
            *(float2*)&out[i1] = o1;
        }
    }
}

// ---------------------------------------------------------------------------
// Host launcher
// ---------------------------------------------------------------------------
extern "C" void kernel_launch(void* const* d_in, const int* in_sizes, int n_in,
                              void* d_out, int out_size)
{
    const float*         src   = (const float*)d_in[0];
    const unsigned char* pmask = (const unsigned char*)d_in[1];
    const float* n1w  = (const float*)d_in[2];
    const float* n1b  = (const float*)d_in[3];
    const float* qkvw = (const float*)d_in[4];
    const float* qkvb = (const float*)d_in[5];
    const float* outw = (const float*)d_in[6];
    const float* outb = (const float*)d_in[7];
    const float* rpb  = (const float*)d_in[8];
    const float* n2w  = (const float*)d_in[9];
    const float* n2b  = (const float*)d_in[10];
    const float* l1w  = (const float*)d_in[11];
    const float* l1b  = (const float*)d_in[12];
    const float* l2w  = (const float*)d_in[13];
    const float* l2b  = (const float*)d_in[14];
    float* outp = (float*)d_out;

    float *pool, *res1;
    cudaGetSymbolAddress((void**)&pool, g_pool);
    cudaGetSymbolAddress((void**)&res1, g_res1);

    float* src2w = pool;                 // [288][256][400]
    float* qkv   = pool + OFF_QKV;       // [288][768][400]
    float* attno = pool;                 // reuse (src2w dead after conv)
    float* ln2   = pool;                 // reuse (attno dead after outproj)
    float* hid   = pool + OFF_HID;       // [2048][57600], reuses qkv region

    cudaFuncSetAttribute(k_conv_mma, cudaFuncAttributeMaxDynamicSharedMemorySize,
                         CV_SMEM_BYTES);
    cudaFuncSetAttribute(k_attn, cudaFuncAttributeMaxDynamicSharedMemorySize,
                         ATTN_SMEM_BYTES);

    // 1. LN1 + window partition
    k_ln_win<<<dim3(LDIM, BATCH), 256>>>(src, n1w, n1b, src2w);

    // 2. windowed 3x3 conv QKV (tf32 mma implicit GEMM)
    k_conv_mma<<<dim3(5, 6, NWIN), 256, CV_SMEM_BYTES>>>(src2w, qkvw, qkvb, qkv);

    // 3. attention per (head, window)
    k_attn<<<dim3(NHEAD, NWIN), 256, ATTN_SMEM_BYTES>>>(qkv, rpb, pmask, attno);

    // 4. out-proj + merge + residual
    k_outproj<<<dim3(5, 4, NWIN), 256>>>(attno, outw, outb, src, res1);

    // 5. LN2
    k_ln_nchw<<<dim3(LDIM, BATCH), 256>>>(res1, n2w, n2b, ln2);

    // 6/7. FFN per batch (full-batch hidden buffer, tf32 mma)
    for (int b = 0; b < BATCH; b++) {
        k_ffn1_mma<<<dim3(450, 16), 256>>>(ln2, l1w, l1b, hid, b);
        k_ffn2_mma<<<dim3(450, 2),  256>>>(hid, l2w, l2b, res1, pmask, outp, b);
    }
}

// round 17
// speedup vs baseline: 2.6785x; 1.0003x over previous
#include <cuda_runtime.h>
#include <cuda_bf16.h>
#include <cstdint>

// ---------------------------------------------------------------------------
// Problem constants
// ---------------------------------------------------------------------------
#define BATCH   2
#define CCH     256
#define LDIM    240
#define LW      20
#define NWH     12                 // windows per side
#define NWIN    288                // BATCH * 12 * 12
#define FPX     400                // LW*LW
#define NHEAD   8
#define HD      32
#define DFF     2048
#define LL      57600              // LDIM*LDIM
#define EPSLN   1e-5f
#define SCALING 0.17677669529663687f   // 32^-0.5

// scratch pool (float counts)
#define SZ_SRC2W  29491200ull          // NWIN*CCH*FPX
#define SZ_HID    117964800ull         // DFF * LL (one batch)
#define POOL_FLOATS (SZ_SRC2W + SZ_HID)
#define OFF_QKV   SZ_SRC2W             // qkv needs 88473600 <= SZ_HID
#define OFF_HID   SZ_SRC2W

__device__ float g_pool[POOL_FLOATS];
__device__ float g_res1[BATCH * CCH * LL];

// ---------------------------------------------------------------------------
// tf32 mma helpers
// ---------------------------------------------------------------------------
__device__ __forceinline__ uint32_t f2t(float f) {
    uint32_t u;
    asm("cvt.rna.tf32.f32 %0, %1;" : "=r"(u) : "f"(f));
    return u;
}

__device__ __forceinline__ void mma_tf32(float* c, const uint32_t* a,
                                         uint32_t b0, uint32_t b1) {
    asm volatile(
        "mma.sync.aligned.m16n8k8.row.col.f32.tf32.tf32.f32 "
        "{%0,%1,%2,%3}, {%4,%5,%6,%7}, {%8,%9}, {%0,%1,%2,%3};\n"
        : "+f"(c[0]), "+f"(c[1]), "+f"(c[2]), "+f"(c[3])
        : "r"(a[0]), "r"(a[1]), "r"(a[2]), "r"(a[3]), "r"(b0), "r"(b1));
}

// ---------------------------------------------------------------------------
// K1a: LayerNorm over C + window partition   src[B,C,L,L] -> src2w[w][c][p]
// ---------------------------------------------------------------------------
__global__ __launch_bounds__(256) void k_ln_win(
    const float* __restrict__ src, const float* __restrict__ g,
    const float* __restrict__ bt, float* __restrict__ dst)
{
    int y = blockIdx.x, b = blockIdx.y;
    int x = threadIdx.x;
    if (x >= LDIM) return;
    const float* p = src + (size_t)b * CCH * LL + (size_t)y * LDIM + x;
    float s = 0.f, s2 = 0.f;
    for (int c = 0; c < CCH; c++) {
        float v = p[(size_t)c * LL];
        s += v; s2 += v * v;
    }
    float m  = s * (1.f / CCH);
    float vr = s2 * (1.f / CCH) - m * m;
    float r  = rsqrtf(vr + EPSLN);
    int wdx = b * 144 + (y / LW) * NWH + (x / LW);
    int pp  = (y % LW) * LW + (x % LW);
    float* q = dst + (size_t)wdx * CCH * FPX + pp;
    for (int c = 0; c < CCH; c++)
        q[(size_t)c * FPX] = (p[(size_t)c * LL] - m) * r * g[c] + bt[c];
}

// K1b: LayerNorm over C, NCHW in, NCHW out
__global__ __launch_bounds__(256) void k_ln_nchw(
    const float* __restrict__ src, const float* __restrict__ g,
    const float* __restrict__ bt, float* __restrict__ dst)
{
    int y = blockIdx.x, b = blockIdx.y;
    int x = threadIdx.x;
    if (x >= LDIM) return;
    size_t base = (size_t)b * CCH * LL + (size_t)y * LDIM + x;
    const float* p = src + base;
    float s = 0.f, s2 = 0.f;
    for (int c = 0; c < CCH; c++) {
        float v = p[(size_t)c * LL];
        s += v; s2 += v * v;
    }
    float m  = s * (1.f / CCH);
    float vr = s2 * (1.f / CCH) - m * m;
    float r  = rsqrtf(vr + EPSLN);
    float* q = dst + base;
    for (int c = 0; c < CCH; c++)
        q[(size_t)c * LL] = (p[(size_t)c * LL] - m) * r * g[c] + bt[c];
}

// ---------------------------------------------------------------------------
// K2: windowed 3x3 conv QKV as implicit GEMM with tf32 mma
//     C[768,400] = W[768, 2304] x im2col(X)[2304, 400] per window
//     Block: 128 oc x 80 px, K chunks of 72 (8 channels x 9 taps)
// ---------------------------------------------------------------------------
#define CV_AS_STRIDE 76
#define CV_BS_STRIDE 88
#define CV_AS (128 * CV_AS_STRIDE)
#define CV_BS (72 * CV_BS_STRIDE)
#define CV_SMEM_BYTES ((CV_AS + CV_BS) * 4)

__global__ __launch_bounds__(256, 2) void k_conv_mma(
    const float* __restrict__ xin, const float* __restrict__ wq,
    const float* __restrict__ bq, float* __restrict__ out)
{
    extern __shared__ uint32_t sm[];
    uint32_t* A_s = sm;              // [128][76] (72 used)
    uint32_t* B_s = sm + CV_AS;      // [72][88]  (80 used)

    int w   = blockIdx.z;
    int oc0 = blockIdx.y * 128;
    int px0 = blockIdx.x * 80;
    int tid  = threadIdx.x;
    int lane = tid & 31, wid = tid >> 5;
    int warp_m = wid >> 1;           // 0..3 -> 32 oc each
    int warp_n = wid & 1;            // 0..1 -> 40 px each

    float acc[2][5][4];
#pragma unroll
    for (int mt = 0; mt < 2; mt++)
#pragma unroll
        for (int nt = 0; nt < 5; nt++)
#pragma unroll
            for (int r = 0; r < 4; r++) acc[mt][nt][r] = 0.f;

    // B-build precompute: thread -> (tap-row group g, pixel pxl)
    int g    = tid / 80;             // 0..2 valid (tid < 240)
    int pxl  = tid - g * 80;
    int pabs = px0 + pxl;
    int row0 = pabs / LW, col0 = pabs % LW;
    int rB   = row0 + (g - 1);
    bool rok = (rB >= 0) && (rB < LW) && (tid < 240);
    bool okc[3];
    int  offt[3];
#pragma unroll
    for (int tt = 0; tt < 3; tt++) {
        int cc   = col0 + tt - 1;
        okc[tt]  = rok && (cc >= 0) && (cc < LW);
        offt[tt] = rB * LW + cc;
    }

    const float* xb = xin + (size_t)w * CCH * FPX;
    int arow = tid >> 1, ahalf = tid & 1;

    for (int c0 = 0; c0 < CCH; c0 += 8) {
        // ---- stage A (weights, tf32): row arow, half ahalf (9 f4 each) ----
        const float* wr = wq + (size_t)(oc0 + arow) * 2304 + c0 * 9 + ahalf * 36;
        uint32_t*    ar = A_s + arow * CV_AS_STRIDE + ahalf * 36;
#pragma unroll
        for (int i = 0; i < 9; i++) {
            float4 v = *(const float4*)(wr + i * 4);
            uint4 u; u.x = f2t(v.x); u.y = f2t(v.y); u.z = f2t(v.z); u.w = f2t(v.w);
            *(uint4*)(ar + i * 4) = u;
        }
        // ---- build B (im2col, tf32) straight from gmem ----
        if (tid < 240) {
#pragma unroll 2
            for (int c = 0; c < 8; c++) {
                const float* xr = xb + (size_t)(c0 + c) * FPX;
#pragma unroll
                for (int tt = 0; tt < 3; tt++) {
                    float v = okc[tt] ? xr[offt[tt]] : 0.f;
                    B_s[(c * 9 + g * 3 + tt) * CV_BS_STRIDE + pxl] = f2t(v);
                }
            }
        }
        __syncthreads();

        // ---- compute: 9 k8-steps ----
#pragma unroll
        for (int ks = 0; ks < 9; ks++) {
            uint32_t a[2][4];
#pragma unroll
            for (int mt = 0; mt < 2; mt++) {
                int base = (warp_m * 32 + mt * 16 + (lane >> 2)) * CV_AS_STRIDE
                         + ks * 8 + (lane & 3);
                a[mt][0] = A_s[base];
                a[mt][1] = A_s[base + 8 * CV_AS_STRIDE];
                a[mt][2] = A_s[base + 4];
                a[mt][3] = A_s[base + 8 * CV_AS_STRIDE + 4];
            }
            int rb = ks * 8 + (lane & 3);
#pragma unroll
            for (int nt = 0; nt < 5; nt++) {
                int n = warp_n * 40 + nt * 8 + (lane >> 2);
                uint32_t b0 = B_s[rb * CV_BS_STRIDE + n];
                uint32_t b1 = B_s[(rb + 4) * CV_BS_STRIDE + n];
#pragma unroll
                for (int mt = 0; mt < 2; mt++)
                    mma_tf32(acc[mt][nt], a[mt], b0, b1);
            }
        }
        __syncthreads();
    }

    // ---- epilogue: add bias, write float2 pairs ----
#pragma unroll
    for (int mt = 0; mt < 2; mt++) {
        int m = oc0 + warp_m * 32 + mt * 16 + (lane >> 2);
        float bv0 = bq[m], bv1 = bq[m + 8];
#pragma unroll
        for (int nt = 0; nt < 5; nt++) {
            int px = px0 + warp_n * 40 + nt * 8 + 2 * (lane & 3);
            float2 o0 = make_float2(acc[mt][nt][0] + bv0, acc[mt][nt][1] + bv0);
            float2 o1 = make_float2(acc[mt][nt][2] + bv1, acc[mt][nt][3] + bv1);
            *(float2*)&out[((size_t)w * 768 + m) * FPX + px]     = o0;
            *(float2*)&out[((size_t)w * 768 + m + 8) * FPX + px] = o1;
        }
    }
}

// ---------------------------------------------------------------------------
// K3: windowed attention, one block per (head, window). K/V/Q in smem.
// ---------------------------------------------------------------------------
#define AT_RS 417                      // padded row stride (coprime with 32)
#define ATTN_SMEM_FLOATS (3 * 32 * AT_RS + 1521 + 8 * 416 + 400)
#define ATTN_SMEM_BYTES  (ATTN_SMEM_FLOATS * 4)

__global__ __launch_bounds__(256, 1) void k_attn(
    const float* __restrict__ qkv, const float* __restrict__ rpb,
    const unsigned char* __restrict__ pmask, float* __restrict__ outp)
{
    extern __shared__ float smf[];
    float* q_s    = smf;
    float* k_s    = q_s + 32 * AT_RS;
    float* v_s    = k_s + 32 * AT_RS;
    float* rpb_s  = v_s + 32 * AT_RS;       // 1521
    float* p_s    = rpb_s + 1521;           // 8 * 416
    float* mask_s = p_s + 8 * 416;          // 400
    __shared__ int s_cnt;

    int h = blockIdx.x, w = blockIdx.y;
    int tid = threadIdx.x;
    const size_t base = ((size_t)w * 768 + h * HD) * FPX;

    for (int f = tid; f < HD * FPX; f += 256) {
        int d = f / FPX, j = f % FPX;
        q_s[d * AT_RS + j] = qkv[base + f] * SCALING;
        k_s[d * AT_RS + j] = qkv[base + (size_t)CCH * FPX + f];
        v_s[d * AT_RS + j] = qkv[base + (size_t)2 * CCH * FPX + f];
    }
    for (int f = tid; f < 32 * (AT_RS - FPX); f += 256) {
        int d = f / (AT_RS - FPX), j = FPX + f % (AT_RS - FPX);
        q_s[d * AT_RS + j] = 0.f; k_s[d * AT_RS + j] = 0.f; v_s[d * AT_RS + j] = 0.f;
    }
    for (int t = tid; t < 1521; t += 256) rpb_s[t] = rpb[t * NHEAD + h];
    if (tid == 0) s_cnt = 0;
    __syncthreads();

    int b = w / 144, wy = (w % 144) / NWH, wx = w % NWH;
    int cnt = 0;
    for (int p = tid; p < FPX; p += 256) {
        int y = wy * LW + p / LW, x = wx * LW + p % LW;
        int m = pmask[(size_t)b * LL + (size_t)y * LDIM + x] ? 1 : 0;
        mask_s[p] = (float)m;
        cnt += m;
    }
    atomicAdd(&s_cnt, cnt);
    __syncthreads();
    bool fully = (s_cnt == FPX);
    for (int p = tid; p < FPX; p += 256)
        mask_s[p] = (!fully && mask_s[p] > 0.5f) ? -1e30f : 0.f;
    __syncthreads();

    int wi = tid >> 5, l = tid & 31;

    for (int t = 0; t < 50; t++) {
        int i  = wi + 8 * t;
        int ri = i / LW, ci = i % LW;
        float s[13];
#pragma unroll
        for (int m = 0; m < 13; m++) s[m] = 0.f;
#pragma unroll 4
        for (int d = 0; d < 32; d++) {
            float qd = q_s[d * AT_RS + i];
#pragma unroll
            for (int m = 0; m < 13; m++)
                s[m] = fmaf(qd, k_s[d * AT_RS + l + 32 * m], s[m]);
        }
        float mx = -1e30f;
#pragma unroll
        for (int m = 0; m < 13; m++) {
            int j = l + 32 * m;
            if (j < FPX) {
                int rj = j / LW, cj = j % LW;
                int dr = rj - ri; if (dr < 0) dr += 39;
                int dc = cj - ci; if (dc < 0) dc += 39;
                s[m] += rpb_s[dr * 39 + dc] + mask_s[j];
            } else s[m] = -1e30f;
            mx = fmaxf(mx, s[m]);
        }
#pragma unroll
        for (int o = 16; o > 0; o >>= 1)
            mx = fmaxf(mx, __shfl_xor_sync(0xffffffffu, mx, o));
        float sum = 0.f;
#pragma unroll
        for (int m = 0; m < 13; m++) { s[m] = __expf(s[m] - mx); sum += s[m]; }
#pragma unroll
        for (int o = 16; o > 0; o >>= 1)
            sum += __shfl_xor_sync(0xffffffffu, sum, o);
        float inv = 1.f / sum;
#pragma unroll
        for (int m = 0; m < 13; m++)
            p_s[wi * 416 + l + 32 * m] = s[m] * inv;
        __syncwarp();

        // AV: lane == d
        float acc = 0.f;
        const float* vrow = v_s + l * AT_RS;
        const float* prow = p_s + wi * 416;
#pragma unroll 8
        for (int j = 0; j < FPX; j++)
            acc = fmaf(prow[j], vrow[j], acc);
        outp[((size_t)w * CCH + h * HD + l) * FPX + i] = acc;
        __syncwarp();
    }
}

// ---------------------------------------------------------------------------
// K4: 1x1 out-proj + window merge + residual -> res1 (NCHW)
// ---------------------------------------------------------------------------
__global__ __launch_bounds__(256) void k_outproj(
    const float* __restrict__ ain, const float* __restrict__ wgt,
    const float* __restrict__ bias, const float* __restrict__ src,
    float* __restrict__ res)
{
    __shared__ float Ws[32 * 65];
    __shared__ float Xs[32 * 80];
    int w   = blockIdx.z;
    int co0 = blockIdx.y * 64;
    int px0 = blockIdx.x * 80;
    int tid = threadIdx.x, tco = tid >> 4, tpx = tid & 15;

    float acc[4][5];
#pragma unroll
    for (int i = 0; i < 4; i++)
#pragma unroll
        for (int j = 0; j < 5; j++) acc[i][j] = 0.f;

    for (int c0 = 0; c0 < CCH; c0 += 32) {
#pragma unroll
        for (int m = 0; m < 8; m++) {
            int f = m * 256 + tid;
            int cl = f >> 5, kk = f & 31;
            Ws[kk * 65 + cl] = wgt[(size_t)(co0 + cl) * CCH + c0 + kk];
        }
#pragma unroll
        for (int m = 0; m < 10; m++) {
            int f = m * 256 + tid;
            int kk = f / 80, pl = f % 80;
            Xs[kk * 80 + pl] = ain[((size_t)w * CCH + c0 + kk) * FPX + px0 + pl];
        }
        __syncthreads();
#pragma unroll
        for (int kk = 0; kk < 32; kk++) {
            float a[4], xv[5];
#pragma unroll
            for (int i = 0; i < 4; i++) a[i] = Ws[kk * 65 + tco + 16 * i];
#pragma unroll
            for (int j = 0; j < 5; j++) xv[j] = Xs[kk * 80 + tpx + 16 * j];
#pragma unroll
            for (int i = 0; i < 4; i++)
#pragma unroll
                for (int j = 0; j < 5; j++)
                    acc[i][j] = fmaf(a[i], xv[j], acc[i][j]);
        }
        __syncthreads();
    }

    int b = w / 144, wy = (w % 144) / NWH, wx = w % NWH;
#pragma unroll
    for (int i = 0; i < 4; i++) {
        int co  = co0 + tco + 16 * i;
        float bb = bias[co];
#pragma unroll
        for (int j = 0; j < 5; j++) {
            int p = px0 + tpx + 16 * j;
            int y = wy * LW + p / LW;
            int x = wx * LW + p % LW;
            size_t idx = ((size_t)(b * CCH + co) * LDIM + y) * LDIM + x;
            res[idx] = src[idx] + acc[i][j] + bb;
        }
    }
}

// ---------------------------------------------------------------------------
// K6: FFN1 via tf32 mma:  hid = relu(W1 x + b1),  [2048,256] x [256,57600]
// Block 128x128, K chunks of 32. Grid (450, 16) per batch.
// ---------------------------------------------------------------------------
#define F_AS_STRIDE 36
#define F_BS_STRIDE 136

__global__ __launch_bounds__(256, 2) void k_ffn1_mma(
    const float* __restrict__ x, const float* __restrict__ w1,
    const float* __restrict__ b1, float* __restrict__ hid, int b)
{
    __shared__ uint32_t A_s[128 * F_AS_STRIDE];
    __shared__ uint32_t B_s[32 * F_BS_STRIDE];

    int px0 = blockIdx.x * 128;
    int co0 = blockIdx.y * 128;
    int tid  = threadIdx.x;
    int lane = tid & 31, wid = tid >> 5;
    int warp_m = wid >> 2;           // 0..1 -> 64 rows
    int warp_n = wid & 3;            // 0..3 -> 32 cols

    float acc[4][4][4];
#pragma unroll
    for (int mt = 0; mt < 4; mt++)
#pragma unroll
        for (int nt = 0; nt < 4; nt++)
#pragma unroll
            for (int r = 0; r < 4; r++) acc[mt][nt][r] = 0.f;

    for (int c0 = 0; c0 < CCH; c0 += 32) {
#pragma unroll
        for (int i = 0; i < 4; i++) {
            int f = i * 256 + tid;
            int row = f >> 3, j = f & 7;
            float4 v = *(const float4*)(w1 + (size_t)(co0 + row) * CCH + c0 + j * 4);
            uint4 u; u.x = f2t(v.x); u.y = f2t(v.y); u.z = f2t(v.z); u.w = f2t(v.w);
            *(uint4*)(A_s + row * F_AS_STRIDE + j * 4) = u;
        }
#pragma unroll
        for (int i = 0; i < 4; i++) {
            int f = i * 256 + tid;
            int row = f >> 5, j = f & 31;
            float4 v = *(const float4*)(x + (size_t)(b * CCH + c0 + row) * LL + px0 + j * 4);
            uint4 u; u.x = f2t(v.x); u.y = f2t(v.y); u.z = f2t(v.z); u.w = f2t(v.w);
            *(uint4*)(B_s + row * F_BS_STRIDE + j * 4) = u;
        }
        __syncthreads();

#pragma unroll
        for (int ks = 0; ks < 4; ks++) {
            uint32_t a[4][4];
#pragma unroll
            for (int mt = 0; mt < 4; mt++) {
                int base = (warp_m * 64 + mt * 16 + (lane >> 2)) * F_AS_STRIDE
                         + ks * 8 + (lane & 3);
                a[mt][0] = A_s[base];
                a[mt][1] = A_s[base + 8 * F_AS_STRIDE];
                a[mt][2] = A_s[base + 4];
                a[mt][3] = A_s[base + 8 * F_AS_STRIDE + 4];
            }
            int rb = ks * 8 + (lane & 3);
#pragma unroll
            for (int nt = 0; nt < 4; nt++) {
                int n = warp_n * 32 + nt * 8 + (lane >> 2);
                uint32_t b0 = B_s[rb * F_BS_STRIDE + n];
                uint32_t b1 = B_s[(rb + 4) * F_BS_STRIDE + n];
#pragma unroll
                for (int mt = 0; mt < 4; mt++)
                    mma_tf32(acc[mt][nt], a[mt], b0, b1);
            }
        }
        __syncthreads();
    }

#pragma unroll
    for (int mt = 0; mt < 4; mt++) {
        int m = co0 + warp_m * 64 + mt * 16 + (lane >> 2);
        float bv0 = b1[m], bv1 = b1[m + 8];
#pragma unroll
        for (int nt = 0; nt < 4; nt++) {
            int n = px0 + warp_n * 32 + nt * 8 + 2 * (lane & 3);
            float2 o0 = make_float2(fmaxf(acc[mt][nt][0] + bv0, 0.f),
                                    fmaxf(acc[mt][nt][1] + bv0, 0.f));
            float2 o1 = make_float2(fmaxf(acc[mt][nt][2] + bv1, 0.f),
                                    fmaxf(acc[mt][nt][3] + bv1, 0.f));
            *(float2*)&hid[(size_t)m * LL + n]       = o0;
            *(float2*)&hid[(size_t)(m + 8) * LL + n] = o1;
        }
    }
}

// ---------------------------------------------------------------------------
// K7: FFN2 via tf32 mma + residual + padding mask -> d_out
//     [256,2048] x [2048,57600]. Grid (450, 2) per batch.
// ---------------------------------------------------------------------------
__global__ __launch_bounds__(256, 2) void k_ffn2_mma(
    const float* __restrict__ hid, const float* __restrict__ w2,
    const float* __restrict__ b2, const float* __restrict__ res1,
    const unsigned char* __restrict__ pmask, float* __restrict__ out, int b)
{
    __shared__ uint32_t A_s[128 * F_AS_STRIDE];
    __shared__ uint32_t B_s[32 * F_BS_STRIDE];

    int px0 = blockIdx.x * 128;
    int co0 = blockIdx.y * 128;
    int tid  = threadIdx.x;
    int lane = tid & 31, wid = tid >> 5;
    int warp_m = wid >> 2;
    int warp_n = wid & 3;

    float acc[4][4][4];
#pragma unroll
    for (int mt = 0; mt < 4; mt++)
#pragma unroll
        for (int nt = 0; nt < 4; nt++)
#pragma unroll
            for (int r = 0; r < 4; r++) acc[mt][nt][r] = 0.f;

    for (int c0 = 0; c0 < DFF; c0 += 32) {
#pragma unroll
        for (int i = 0; i < 4; i++) {
            int f = i * 256 + tid;
            int row = f >> 3, j = f & 7;
            float4 v = *(const float4*)(w2 + (size_t)(co0 + row) * DFF + c0 + j * 4);
            uint4 u; u.x = f2t(v.x); u.y = f2t(v.y); u.z = f2t(v.z); u.w = f2t(v.w);
            *(uint4*)(A_s + row * F_AS_STRIDE + j * 4) = u;
        }
#pragma unroll
        for (int i = 0; i < 4; i++) {
            int f = i * 256 + tid;
            int row = f >> 5, j = f & 31;
            float4 v = *(const float4*)(hid + (size_t)(c0 + row) * LL + px0 + j * 4);
            uint4 u; u.x = f2t(v.x); u.y = f2t(v.y); u.z = f2t(v.z); u.w = f2t(v.w);
            *(uint4*)(B_s + row * F_BS_STRIDE + j * 4) = u;
        }
        __syncthreads();

#pragma unroll
        for (int ks = 0; ks < 4; ks++) {
            uint32_t a[4][4];
#pragma unroll
            for (int mt = 0; mt < 4; mt++) {
                int base = (warp_m * 64 + mt * 16 + (lane >> 2)) * F_AS_STRIDE
                         + ks * 8 + (lane & 3);
                a[mt][0] = A_s[base];
                a[mt][1] = A_s[base + 8 * F_AS_STRIDE];
                a[mt][2] = A_s[base + 4];
                a[mt][3] = A_s[base + 8 * F_AS_STRIDE + 4];
            }
            int rb = ks * 8 + (lane & 3);
#pragma unroll
            for (int nt = 0; nt < 4; nt++) {
                int n = warp_n * 32 + nt * 8 + (lane >> 2);
                uint32_t b0 = B_s[rb * F_BS_STRIDE + n];
                uint32_t b1 = B_s[(rb + 4) * F_BS_STRIDE + n];
#pragma unroll
                for (int mt = 0; mt < 4; mt++)
                    mma_tf32(acc[mt][nt], a[mt], b0, b1);
            }
        }
        __syncthreads();
    }

#pragma unroll
    for (int mt = 0; mt < 4; mt++) {
        int m = co0 + warp_m * 64 + mt * 16 + (lane >> 2);
        float bv0 = b2[m], bv1 = b2[m + 8];
#pragma unroll
        for (int nt = 0; nt < 4; nt++) {
            int n = px0 + warp_n * 32 + nt * 8 + 2 * (lane & 3);
            unsigned char mk0 = pmask[(size_t)b * LL + n];
            unsigned char mk1 = pmask[(size_t)b * LL + n + 1];
            size_t i0 = (size_t)(b * CCH + m) * LL + n;
            size_t i1 = (size_t)(b * CCH + m + 8) * LL + n;
            float2 r0 = *(const float2*)&res1[i0];
            float2 r1 = *(const float2*)&res1[i1];
            float2 o0, o1;
            o0.x = mk0 ? 0.f : (r0.x + acc[mt][nt][0] + bv0);
            o0.y = mk1 ? 0.f : (r0.y + acc[mt][nt][1] + bv0);
            o1.x = mk0 ? 0.f : (r1.x + acc[mt][nt][2] + bv1);
            o1.y = mk1 ? 0.f : (r1.y + acc[mt][nt][3] + bv1);
            *(float2*)&out[i0] = o0;
            *(float2*)&out[i1] = o1;
        }
    }
}

// ---------------------------------------------------------------------------
// Host launcher
// ---------------------------------------------------------------------------
extern "C" void kernel_launch(void* const* d_in, const int* in_sizes, int n_in,
                              void* d_out, int out_size)
{
    const float*         src   = (const float*)d_in[0];
    const unsigned char* pmask = (const unsigned char*)d_in[1];
    const float* n1w  = (const float*)d_in[2];
    const float* n1b  = (const float*)d_in[3];
    const float* qkvw = (const float*)d_in[4];
    const float* qkvb = (const float*)d_in[5];
    const float* outw = (const float*)d_in[6];
    const float* outb = (const float*)d_in[7];
    const float* rpb  = (const float*)d_in[8];
    const float* n2w  = (const float*)d_in[9];
    const float* n2b  = (const float*)d_in[10];
    const float* l1w  = (const float*)d_in[11];
    const float* l1b  = (const float*)d_in[12];
    const float* l2w  = (const float*)d_in[13];
    const float* l2b  = (const float*)d_in[14];
    float* outp = (float*)d_out;

    float *pool, *res1;
    cudaGetSymbolAddress((void**)&pool, g_pool);
    cudaGetSymbolAddress((void**)&res1, g_res1);

    float* src2w = pool;                 // [288][256][400]
    float* qkv   = pool + OFF_QKV;       // [288][768][400]
    float* attno = pool;                 // reuse (src2w dead after conv)
    float* ln2   = pool;                 // reuse (attno dead after outproj)
    float* hid   = pool + OFF_HID;       // [2048][57600], reuses qkv region

    cudaFuncSetAttribute(k_conv_mma, cudaFuncAttributeMaxDynamicSharedMemorySize,
                         CV_SMEM_BYTES);
    cudaFuncSetAttribute(k_attn, cudaFuncAttributeMaxDynamicSharedMemorySize,
                         ATTN_SMEM_BYTES);

    // 1. LN1 + window partition
    k_ln_win<<<dim3(LDIM, BATCH), 256>>>(src, n1w, n1b, src2w);

    // 2. windowed 3x3 conv QKV (tf32 mma implicit GEMM)
    k_conv_mma<<<dim3(5, 6, NWIN), 256, CV_SMEM_BYTES>>>(src2w, qkvw, qkvb, qkv);

    // 3. attention per (head, window)
    k_attn<<<dim3(NHEAD, NWIN), 256, ATTN_SMEM_BYTES>>>(qkv, rpb, pmask, attno);

    // 4. out-proj + merge + residual
    k_outproj<<<dim3(5, 4, NWIN), 256>>>(attno, outw, outb, src, res1);

    // 5. LN2
    k_ln_nchw<<<dim3(LDIM, BATCH), 256>>>(res1, n2w, n2b, ln2);

    // 6/7. FFN per batch (full-batch hidden buffer, tf32 mma)
    for (int b = 0; b < BATCH; b++) {
        k_ffn1_mma<<<dim3(450, 16), 256>>>(ln2, l1w, l1b, hid, b);
        k_ffn2_mma<<<dim3(450, 2),  256>>>(hid, l2w, l2b, res1, pmask, outp, b);
    }
}